// round 13
// baseline (speedup 1.0000x reference)
#include <cuda_runtime.h>
#include <cstdint>

// Conv4d via tf32 mma.sync.m16n8k8 implicit GEMM, round 13.
// R11 compute core + reg diet (32-bit A offsets, no explicit B prefetch)
// + __launch_bounds__(128,5): 5 CTAs/SM, 20 warps -> higher tensor occupancy.
// Epilogue reverted to direct scattered stores (R12 transpose regressed).

__device__ __forceinline__ float to_tf32(float v) {
    float r; asm("cvt.rna.tf32.f32 %0, %1;" : "=f"(r) : "f"(v)); return r;
}
__device__ __forceinline__ void mma16n8k8(float* d,
    uint32_t a0, uint32_t a1, uint32_t a2, uint32_t a3, uint32_t b0, uint32_t b1) {
    asm volatile("mma.sync.aligned.m16n8k8.row.col.f32.tf32.tf32.f32 "
                 "{%0,%1,%2,%3}, {%4,%5,%6,%7}, {%8,%9}, {%0,%1,%2,%3};"
                 : "+f"(d[0]), "+f"(d[1]), "+f"(d[2]), "+f"(d[3])
                 : "r"(a0), "r"(a1), "r"(a2), "r"(a3), "r"(b0), "r"(b1));
}

// B fragments: [kt][tap][p(2)][lane(32)] float4 = (b0,b1 of nt=2p | b0,b1 of nt=2p+1)
__device__ float4 g_fB[3 * 27 * 2 * 32];

__global__ void prep_fB(const float* __restrict__ weight) {
    int i = blockIdx.x * blockDim.x + threadIdx.x;
    if (i >= 5184) return;
    int lane = i & 31;
    int p    = (i >> 5) & 1;
    int kttap = i >> 6;
    int tap = kttap % 27, kt = kttap / 27;
    int g = lane >> 2, k0 = lane & 3;
    int co0 = (2 * p) * 8 + g, co1 = co0 + 8;
    float4 f;
    f.x = to_tf32(weight[((kt * 32 + co0) * 8 + k0) * 27 + tap]);
    f.y = to_tf32(weight[((kt * 32 + co0) * 8 + k0 + 4) * 27 + tap]);
    f.z = to_tf32(weight[((kt * 32 + co1) * 8 + k0) * 27 + tap]);
    f.w = to_tf32(weight[((kt * 32 + co1) * 8 + k0 + 4) * 27 + tap]);
    g_fB[i] = f;
}

#define NT 128
#define PLANE 968                 // 4*5*48=960 +8 pad: c-plane bank offsets {0,8,16,24}

__global__ void __launch_bounds__(NT, 5) conv4d_mma(
    const float* __restrict__ x, const float* __restrict__ bias,
    float* __restrict__ out)
{
    __shared__ __align__(16) float slab[8 * PLANE];   // [ci8][dd4][hh5][ww48] 31 KB
    __shared__ float sbias[32];

    const int tid  = threadIdx.x;
    const int wid  = tid >> 5, lane = tid & 31;
    const int g    = lane >> 2, c = lane & 3;
    const int dsel = wid >> 1;
    const int mhalf= wid & 1;

    const int hi  = blockIdx.x;                // 0..13
    const int dy0 = blockIdx.y * 2;
    const int bz  = blockIdx.z;
    const int h0  = (hi < 13) ? hi * 3 : 37;   // overlap rows recompute same values
    const int b   = bz >> 4;
    const int t   = bz & 15;

    if (tid < 32) {
        float s = 0.f;
        #pragma unroll
        for (int kt = 0; kt < 3; ++kt) {
            int tf = t + kt - 1;
            if (tf >= 0 && tf < 16) s += bias[kt * 32 + tid];
        }
        sbias[tid] = s;
    }
    for (int i = tid; i < 8 * PLANE; i += NT) slab[i] = 0.f;   // halo stays 0

    // A row offsets (32-bit smem indices): rows r = mhalf*64 + mt*16 + g + j*8
    int aOff[4][2];
    #pragma unroll
    for (int mt = 0; mt < 4; ++mt)
        #pragma unroll
        for (int j = 0; j < 2; ++j) {
            int r  = mhalf * 64 + mt * 16 + g + j * 8;
            int rr = (r < 126) ? r : 125;
            int hl = rr / 42, wi = rr - hl * 42;
            aOff[mt][j] = c * PLANE + dsel * 240 + hl * 48 + wi + 3;
        }

    float acc[4][4][4];
    #pragma unroll
    for (int mt = 0; mt < 4; ++mt)
        #pragma unroll
        for (int nt = 0; nt < 4; ++nt)
            #pragma unroll
            for (int k = 0; k < 4; ++k) acc[mt][nt][k] = 0.f;

    for (int kt = 0; kt < 3; ++kt) {
        const int tf = t + kt - 1;
        if (tf < 0 || tf >= 16) continue;       // uniform across block
        __syncthreads();

        // ---- stage slab: 8ci x 4dd x 5hh rows, 10 float4 per row ----
        const float* xg = x + b * 8192000 + tf * 64000;
        for (int idx = tid; idx < 1600; idx += NT) {
            int ci  = idx / 200;
            int rem = idx - ci * 200;
            int row = rem / 10, q = rem - row * 10;
            int dd  = row / 5,  hh = row - dd * 5;
            int gd = dy0 + dd - 1, gh = h0 + hh - 1;
            if ((unsigned)gd < 40u && (unsigned)gh < 40u) {
                float4 v = *(const float4*)(xg + ci * 1024000 + gd * 1600 + gh * 40 + q * 4);
                v.x = to_tf32(v.x); v.y = to_tf32(v.y);
                v.z = to_tf32(v.z); v.w = to_tf32(v.w);
                *(float4*)(slab + ci * PLANE + dd * 240 + hh * 48 + 4 + q * 4) = v;
            }
        }
        __syncthreads();

        // ---- 27 taps fully unrolled, B loaded per tap (L1-resident) ----
        const float4* fb = g_fB + (kt * 27) * 64 + lane;
        #pragma unroll
        for (int tap = 0; tap < 27; ++tap) {
            const int kd = tap / 9, kh = (tap % 9) / 3, kw = tap % 3;
            const int sh = kd * 240 + kh * 48 + kw;          // immediate
            const float4 f0 = __ldg(fb + tap * 64);
            const float4 f1 = __ldg(fb + tap * 64 + 32);
            const uint32_t bb0 = __float_as_uint(f0.x), bb1 = __float_as_uint(f0.y);
            const uint32_t bb2 = __float_as_uint(f0.z), bb3 = __float_as_uint(f0.w);
            const uint32_t bc0 = __float_as_uint(f1.x), bc1 = __float_as_uint(f1.y);
            const uint32_t bc2 = __float_as_uint(f1.z), bc3 = __float_as_uint(f1.w);
            #pragma unroll
            for (int mt = 0; mt < 4; ++mt) {
                uint32_t a0 = __float_as_uint(slab[aOff[mt][0] + sh]);
                uint32_t a1 = __float_as_uint(slab[aOff[mt][1] + sh]);
                uint32_t a2 = __float_as_uint(slab[aOff[mt][0] + sh + 4 * PLANE]);
                uint32_t a3 = __float_as_uint(slab[aOff[mt][1] + sh + 4 * PLANE]);
                mma16n8k8(acc[mt][0], a0, a1, a2, a3, bb0, bb1);
                mma16n8k8(acc[mt][1], a0, a1, a2, a3, bb2, bb3);
                mma16n8k8(acc[mt][2], a0, a1, a2, a3, bc0, bc1);
                mma16n8k8(acc[mt][3], a0, a1, a2, a3, bc2, bc3);
            }
        }
    }

    // ---- epilogue: bias + masked scattered stores (R11 style) ----
    const int dyw = dy0 + dsel;
    #pragma unroll
    for (int mt = 0; mt < 4; ++mt) {
        #pragma unroll
        for (int j = 0; j < 2; ++j) {
            int r = mhalf * 64 + mt * 16 + g + j * 8;
            if (r >= 126) continue;
            int hl = r / 42, wi = r - hl * 42;
            if (wi >= 40) continue;
            int sp = dyw * 1600 + (h0 + hl) * 40 + wi;
            #pragma unroll
            for (int nt = 0; nt < 4; ++nt) {
                int co = nt * 8 + 2 * c;
                out[((b * 32 + co) * 16 + t) * 64000 + sp]     = acc[mt][nt][j * 2]     + sbias[co];
                out[((b * 32 + co + 1) * 16 + t) * 64000 + sp] = acc[mt][nt][j * 2 + 1] + sbias[co + 1];
            }
        }
    }
}

extern "C" void kernel_launch(void* const* d_in, const int* in_sizes, int n_in,
                              void* d_out, int out_size) {
    const float* x = nullptr; const float* w = nullptr; const float* bias = nullptr;
    for (int i = 0; i < n_in; ++i) {
        if (in_sizes[i] == 16384000)    x    = (const float*)d_in[i];
        else if (in_sizes[i] == 20736)  w    = (const float*)d_in[i];
        else if (in_sizes[i] == 96)     bias = (const float*)d_in[i];
    }
    float* out = (float*)d_out;
    prep_fB<<<21, 256>>>(w);
    dim3 grid(14, 20, 32);
    conv4d_mma<<<grid, NT>>>(x, bias, out);
}

// round 14
// speedup vs baseline: 1.5863x; 1.5863x over previous
#include <cuda_runtime.h>
#include <cuda_fp16.h>
#include <cstdint>

// Conv4d via fp16 mma.sync m16n8k16 implicit GEMM, round 14.
// fp16 has the same 11-bit significand as tf32 (range irrelevant here), but
// k16 packs 2 taps per MMA: instruction count -48%, A-LDS -50% vs R11.
// Warp = 64m x 32co, CTA = 2 d-layers; taps paired (2p,2p+1), tail tap 26 via k8.

__device__ __forceinline__ void mma_k16(float* d,
    uint32_t a0, uint32_t a1, uint32_t a2, uint32_t a3, uint32_t b0, uint32_t b1) {
    asm volatile("mma.sync.aligned.m16n8k16.row.col.f32.f16.f16.f32 "
                 "{%0,%1,%2,%3}, {%4,%5,%6,%7}, {%8,%9}, {%0,%1,%2,%3};"
                 : "+f"(d[0]), "+f"(d[1]), "+f"(d[2]), "+f"(d[3])
                 : "r"(a0), "r"(a1), "r"(a2), "r"(a3), "r"(b0), "r"(b1));
}
__device__ __forceinline__ void mma_k8(float* d,
    uint32_t a0, uint32_t a1, uint32_t b0) {
    asm volatile("mma.sync.aligned.m16n8k8.row.col.f32.f16.f16.f32 "
                 "{%0,%1,%2,%3}, {%4,%5}, {%6}, {%0,%1,%2,%3};"
                 : "+f"(d[0]), "+f"(d[1]), "+f"(d[2]), "+f"(d[3])
                 : "r"(a0), "r"(a1), "r"(b0));
}

// B fragments: [kt][slot27][lane32] float4; slot s holds, for nt=0..3,
// half2( W[co=nt*8+g][ci=2c][tap=s], W[co=nt*8+g][ci=2c+1][tap=s] ).
// Pair p uses slots 2p (b0) and 2p+1 (b1); tail k8 uses slot 26.
__device__ float4 g_fB[3 * 27 * 32];

__global__ void prep_fB(const float* __restrict__ weight) {
    int i = blockIdx.x * blockDim.x + threadIdx.x;
    if (i >= 3 * 27 * 32) return;
    int lane = i & 31;
    int slot = (i >> 5) % 27;
    int kt   = i / (27 * 32);
    int g = lane >> 2, c = lane & 3;
    int tap = slot;
    uint32_t u[4];
    #pragma unroll
    for (int nt = 0; nt < 4; ++nt) {
        int co = nt * 8 + g;
        float wlo = weight[((kt * 32 + co) * 8 + 2 * c) * 27 + tap];
        float whi = weight[((kt * 32 + co) * 8 + 2 * c + 1) * 27 + tap];
        __half2 h = __floats2half2_rn(wlo, whi);
        u[nt] = *(uint32_t*)&h;
    }
    g_fB[(kt * 27 + slot) * 32 + lane] = *(float4*)u;
}

#define NT 128
#define PLANEH 968        // per-cipair plane: 4*5*48=960 half2 + 8 pad (bank offsets {0,8,16,24})

__global__ void __launch_bounds__(NT, 4) conv4d_mma(
    const float* __restrict__ x, const float* __restrict__ bias,
    float* __restrict__ out)
{
    __shared__ __align__(16) uint32_t slabh2[4 * PLANEH];  // [cipair4][dd4][hh5][ww48] half2, 15.5 KB
    __shared__ float sbias[32];

    const int tid  = threadIdx.x;
    const int wid  = tid >> 5, lane = tid & 31;
    const int g    = lane >> 2, c = lane & 3;
    const int dsel = wid >> 1;
    const int mhalf= wid & 1;

    const int hi  = blockIdx.x;                // 0..13
    const int dy0 = blockIdx.y * 2;
    const int bz  = blockIdx.z;
    const int h0  = (hi < 13) ? hi * 3 : 37;   // overlap rows recompute same values
    const int b   = bz >> 4;
    const int t   = bz & 15;

    if (tid < 32) {
        float s = 0.f;
        #pragma unroll
        for (int kt = 0; kt < 3; ++kt) {
            int tf = t + kt - 1;
            if (tf >= 0 && tf < 16) s += bias[kt * 32 + tid];
        }
        sbias[tid] = s;
    }
    for (int i = tid; i < 4 * PLANEH; i += NT) slabh2[i] = 0u;   // halo stays 0

    // A row base pointers: rows r = mhalf*64 + mt*16 + g + j*8
    const uint32_t* aBase[4][2];
    #pragma unroll
    for (int mt = 0; mt < 4; ++mt)
        #pragma unroll
        for (int j = 0; j < 2; ++j) {
            int r  = mhalf * 64 + mt * 16 + g + j * 8;
            int rr = (r < 126) ? r : 125;
            int hl = rr / 42, wi = rr - hl * 42;
            aBase[mt][j] = slabh2 + c * PLANEH + dsel * 240 + hl * 48 + wi + 3;
        }

    float acc[4][4][4];
    #pragma unroll
    for (int mt = 0; mt < 4; ++mt)
        #pragma unroll
        for (int nt = 0; nt < 4; ++nt)
            #pragma unroll
            for (int k = 0; k < 4; ++k) acc[mt][nt][k] = 0.f;

    for (int kt = 0; kt < 3; ++kt) {
        const int tf = t + kt - 1;
        if (tf < 0 || tf >= 16) continue;       // uniform across block
        __syncthreads();

        // ---- stage slab: (cipair4, dd4, hh5, q10): 2x LDG.128 -> 4 half2 -> STS.128 ----
        const float* xg = x + b * 8192000 + tf * 64000;
        for (int idx = tid; idx < 800; idx += NT) {
            int cip = idx / 200;
            int rem = idx - cip * 200;
            int row = rem / 10, q = rem - row * 10;
            int dd  = row / 5,  hh = row - dd * 5;
            int gd = dy0 + dd - 1, gh = h0 + hh - 1;
            if ((unsigned)gd < 40u && (unsigned)gh < 40u) {
                const float* p0 = xg + (2 * cip) * 1024000 + gd * 1600 + gh * 40 + q * 4;
                float4 v0 = *(const float4*)p0;
                float4 v1 = *(const float4*)(p0 + 1024000);
                uint32_t h[4];
                __half2 h0v = __floats2half2_rn(v0.x, v1.x); h[0] = *(uint32_t*)&h0v;
                __half2 h1v = __floats2half2_rn(v0.y, v1.y); h[1] = *(uint32_t*)&h1v;
                __half2 h2v = __floats2half2_rn(v0.z, v1.z); h[2] = *(uint32_t*)&h2v;
                __half2 h3v = __floats2half2_rn(v0.w, v1.w); h[3] = *(uint32_t*)&h3v;
                *(uint4*)(slabh2 + cip * PLANEH + dd * 240 + hh * 48 + 4 + q * 4) = *(uint4*)h;
            }
        }
        __syncthreads();

        // ---- 13 tap-pairs (k16) + 1 tail tap (k8), fully unrolled ----
        const float4* fb = g_fB + (kt * 27) * 32 + lane;
        float4 f0 = __ldg(fb);            // slot 0 = b0 of pair 0
        float4 f1 = __ldg(fb + 32);       // slot 1 = b1 of pair 0
        #pragma unroll
        for (int p = 0; p < 13; ++p) {
            const int t0 = 2 * p, t1 = 2 * p + 1;
            const int sh0 = (t0 / 9) * 240 + ((t0 % 9) / 3) * 48 + (t0 % 3);
            const int sh1 = (t1 / 9) * 240 + ((t1 % 9) / 3) * 48 + (t1 % 3);
            float4 nf0, nf1;
            if (p < 12) {
                nf0 = __ldg(fb + (2 * p + 2) * 32);
                nf1 = __ldg(fb + (2 * p + 3) * 32);
            } else {
                nf0 = __ldg(fb + 26 * 32);       // tail k8 B
            }
            const uint32_t b00 = __float_as_uint(f0.x), b01 = __float_as_uint(f0.y);
            const uint32_t b02 = __float_as_uint(f0.z), b03 = __float_as_uint(f0.w);
            const uint32_t b10 = __float_as_uint(f1.x), b11 = __float_as_uint(f1.y);
            const uint32_t b12 = __float_as_uint(f1.z), b13 = __float_as_uint(f1.w);
            #pragma unroll
            for (int mt = 0; mt < 4; ++mt) {
                uint32_t a0 = aBase[mt][0][sh0];
                uint32_t a1 = aBase[mt][1][sh0];
                uint32_t a2 = aBase[mt][0][sh1];
                uint32_t a3 = aBase[mt][1][sh1];
                mma_k16(acc[mt][0], a0, a1, a2, a3, b00, b10);
                mma_k16(acc[mt][1], a0, a1, a2, a3, b01, b11);
                mma_k16(acc[mt][2], a0, a1, a2, a3, b02, b12);
                mma_k16(acc[mt][3], a0, a1, a2, a3, b03, b13);
            }
            f0 = nf0; f1 = nf1;
        }
        // tail: tap 26 (kd=2,kh=2,kw=2), k8; B is in f0
        {
            const int sh = 2 * 240 + 2 * 48 + 2;
            const uint32_t b0 = __float_as_uint(f0.x), b1 = __float_as_uint(f0.y);
            const uint32_t b2 = __float_as_uint(f0.z), b3 = __float_as_uint(f0.w);
            #pragma unroll
            for (int mt = 0; mt < 4; ++mt) {
                uint32_t a0 = aBase[mt][0][sh];
                uint32_t a1 = aBase[mt][1][sh];
                mma_k8(acc[mt][0], a0, a1, b0);
                mma_k8(acc[mt][1], a0, a1, b1);
                mma_k8(acc[mt][2], a0, a1, b2);
                mma_k8(acc[mt][3], a0, a1, b3);
            }
        }
    }

    // ---- epilogue: bias + masked scattered stores (R11 style) ----
    const int dyw = dy0 + dsel;
    #pragma unroll
    for (int mt = 0; mt < 4; ++mt) {
        #pragma unroll
        for (int j = 0; j < 2; ++j) {
            int r = mhalf * 64 + mt * 16 + g + j * 8;
            if (r >= 126) continue;
            int hl = r / 42, wi = r - hl * 42;
            if (wi >= 40) continue;
            int sp = dyw * 1600 + (h0 + hl) * 40 + wi;
            #pragma unroll
            for (int nt = 0; nt < 4; ++nt) {
                int co = nt * 8 + 2 * c;
                out[((b * 32 + co) * 16 + t) * 64000 + sp]     = acc[mt][nt][j * 2]     + sbias[co];
                out[((b * 32 + co + 1) * 16 + t) * 64000 + sp] = acc[mt][nt][j * 2 + 1] + sbias[co + 1];
            }
        }
    }
}

extern "C" void kernel_launch(void* const* d_in, const int* in_sizes, int n_in,
                              void* d_out, int out_size) {
    const float* x = nullptr; const float* w = nullptr; const float* bias = nullptr;
    for (int i = 0; i < n_in; ++i) {
        if (in_sizes[i] == 16384000)    x    = (const float*)d_in[i];
        else if (in_sizes[i] == 20736)  w    = (const float*)d_in[i];
        else if (in_sizes[i] == 96)     bias = (const float*)d_in[i];
    }
    float* out = (float*)d_out;
    prep_fB<<<(3 * 27 * 32 + 255) / 256, 256>>>(w);
    dim3 grid(14, 20, 32);
    conv4d_mma<<<grid, NT>>>(x, bias, out);
}

// round 16
// speedup vs baseline: 1.7017x; 1.0727x over previous
#include <cuda_runtime.h>
#include <cuda_fp16.h>
#include <cstdint>

// Conv4d via fp16 mma.sync m16n8k16 implicit GEMM, round 16.
// = R15 (pre-converted half2 x in gmem + cp.async staging of all 3 tf slabs,
// R14 compute core) with the staging stride bug fixed: 16B chunk = 4 u32,
// so each 40-half2 row needs 10 chunks at stride 4 (was: 5 chunks at stride 8).

__device__ __forceinline__ void mma_k16(float* d,
    uint32_t a0, uint32_t a1, uint32_t a2, uint32_t a3, uint32_t b0, uint32_t b1) {
    asm volatile("mma.sync.aligned.m16n8k16.row.col.f32.f16.f16.f32 "
                 "{%0,%1,%2,%3}, {%4,%5,%6,%7}, {%8,%9}, {%0,%1,%2,%3};"
                 : "+f"(d[0]), "+f"(d[1]), "+f"(d[2]), "+f"(d[3])
                 : "r"(a0), "r"(a1), "r"(a2), "r"(a3), "r"(b0), "r"(b1));
}
__device__ __forceinline__ void mma_k8(float* d,
    uint32_t a0, uint32_t a1, uint32_t b0) {
    asm volatile("mma.sync.aligned.m16n8k8.row.col.f32.f16.f16.f32 "
                 "{%0,%1,%2,%3}, {%4,%5}, {%6}, {%0,%1,%2,%3};"
                 : "+f"(d[0]), "+f"(d[1]), "+f"(d[2]), "+f"(d[3])
                 : "r"(a0), "r"(a1), "r"(b0));
}
__device__ __forceinline__ uint32_t smem_u32(const void* p) {
    uint32_t a;
    asm("{ .reg .u64 t; cvta.to.shared.u64 t, %1; cvt.u32.u64 %0, t; }" : "=r"(a) : "l"(p));
    return a;
}
__device__ __forceinline__ void cp_async16(uint32_t saddr, const void* gaddr) {
    asm volatile("cp.async.ca.shared.global [%0], [%1], 16;" :: "r"(saddr), "l"(gaddr));
}

// ---- pre-baked operands ----
// B fragments: [kt][slot27][lane32] float4; slot s, component nt:
//   half2( W[co=nt*8+g][ci=2c][tap=s], W[co=nt*8+g][ci=2c+1][tap=s] )
__device__ float4 g_fB[3 * 27 * 32];
// x as half2: [b][t][cipair4][d40][h40][w40], half2 = (ci=2cip, ci=2cip+1)
__device__ uint32_t g_xh[2 * 16 * 4 * 64000];

__global__ void prep_fB(const float* __restrict__ weight) {
    int i = blockIdx.x * blockDim.x + threadIdx.x;
    if (i >= 3 * 27 * 32) return;
    int lane = i & 31;
    int slot = (i >> 5) % 27;
    int kt   = i / (27 * 32);
    int g = lane >> 2, c = lane & 3;
    uint32_t u[4];
    #pragma unroll
    for (int nt = 0; nt < 4; ++nt) {
        int co = nt * 8 + g;
        float wlo = weight[((kt * 32 + co) * 8 + 2 * c) * 27 + slot];
        float whi = weight[((kt * 32 + co) * 8 + 2 * c + 1) * 27 + slot];
        __half2 h = __floats2half2_rn(wlo, whi);
        u[nt] = *(uint32_t*)&h;
    }
    g_fB[(kt * 27 + slot) * 32 + lane] = *(float4*)u;
}

__global__ void prep_x(const float* __restrict__ x) {
    int i = blockIdx.x * blockDim.x + threadIdx.x;
    if (i >= 8192000) return;
    int pos = i % 64000;
    int r   = i / 64000;            // (b*16+t)*4 + cip
    int cip = r & 3;
    int bt  = r >> 2;
    int t = bt & 15, b = bt >> 4;
    const float* p = x + b * 8192000 + (2 * cip) * 1024000 + t * 64000 + pos;
    __half2 h = __floats2half2_rn(p[0], p[1024000]);
    g_xh[i] = *(uint32_t*)&h;
}

#define NT 128
#define PLANEH 968        // per-cipair plane: 4*5*48 half2 + 8 pad (bank offs {0,8,16,24})
#define TFS (4 * PLANEH)  // per-tf slab stride = 3872 u32

__global__ void __launch_bounds__(NT, 4) conv4d_mma(
    const float* __restrict__ bias, float* __restrict__ out)
{
    __shared__ __align__(16) uint32_t slab[3 * TFS];   // [tf3][cip4][dd4][hh5][ww48] 46.5 KB
    __shared__ float sbias[32];

    const int tid  = threadIdx.x;
    const int wid  = tid >> 5, lane = tid & 31;
    const int g    = lane >> 2, c = lane & 3;
    const int dsel = wid >> 1;
    const int mhalf= wid & 1;

    const int hi  = blockIdx.x;                // 0..13
    const int dy0 = blockIdx.y * 2;
    const int bz  = blockIdx.z;
    const int h0  = (hi < 13) ? hi * 3 : 37;   // overlap rows recompute same values
    const int b   = bz >> 4;
    const int t   = bz & 15;

    if (tid < 32) {
        float s = 0.f;
        #pragma unroll
        for (int kt = 0; kt < 3; ++kt) {
            int tf = t + kt - 1;
            if (tf >= 0 && tf < 16) s += bias[kt * 32 + tid];
        }
        sbias[tid] = s;
    }
    for (int i = tid; i < 3 * TFS; i += NT) slab[i] = 0u;   // halo/invalid stays 0

    // A row base offsets (u32 indices into slab, per-tf slab added via sk)
    int aOff[4][2];
    #pragma unroll
    for (int mt = 0; mt < 4; ++mt)
        #pragma unroll
        for (int j = 0; j < 2; ++j) {
            int r  = mhalf * 64 + mt * 16 + g + j * 8;
            int rr = (r < 126) ? r : 125;
            int hl = rr / 42, wi = rr - hl * 42;
            aOff[mt][j] = c * PLANEH + dsel * 240 + hl * 48 + wi + 3;
        }

    float acc[4][4][4];
    #pragma unroll
    for (int mt = 0; mt < 4; ++mt)
        #pragma unroll
        for (int nt = 0; nt < 4; ++nt)
            #pragma unroll
            for (int k = 0; k < 4; ++k) acc[mt][nt][k] = 0.f;

    __syncthreads();   // zero-fill visible before cp.async writes land

    // ---- stage all valid tf slabs via cp.async ----
    // 16B chunk = 4 u32 (4 half2 / 4 w-positions); 10 chunks per 40-wide row.
    const uint32_t slab_s = smem_u32(slab);
    #pragma unroll
    for (int kt = 0; kt < 3; ++kt) {
        const int tf = t + kt - 1;
        if ((unsigned)tf >= 16u) continue;
        const uint32_t* xg = g_xh + ((b * 16 + tf) * 4) * 64000;
        for (int idx = tid; idx < 800; idx += NT) {
            int ch = idx % 10;               // chunk within row: u32 offset ch*4
            int r2 = idx / 10;               // 0..79: (cip,dd,hh)
            int hh = r2 % 5;
            int r3 = r2 / 5;                 // 0..15
            int dd = r3 & 3, cip = r3 >> 2;
            int gd = dy0 + dd - 1, gh = h0 + hh - 1;
            if ((unsigned)gd < 40u && (unsigned)gh < 40u) {
                const void* src = xg + cip * 64000 + gd * 1600 + gh * 40 + ch * 4;
                uint32_t dst = slab_s + 4u * (kt * TFS + cip * PLANEH + dd * 240 + hh * 48 + 4 + ch * 4);
                cp_async16(dst, src);
            }
        }
    }
    asm volatile("cp.async.commit_group;");
    asm volatile("cp.async.wait_group 0;" ::: "memory");
    __syncthreads();

    // ---- tap loops: per valid kt, 13 k16 pairs + 1 k8 tail, fully unrolled ----
    #pragma unroll
    for (int kt = 0; kt < 3; ++kt) {
        const int tf = t + kt - 1;
        if ((unsigned)tf >= 16u) continue;
        const uint32_t* sk = slab + kt * TFS;
        const float4* fb = g_fB + (kt * 27) * 32 + lane;
        float4 f0 = fb[0];
        float4 f1 = fb[32];
        #pragma unroll
        for (int p = 0; p < 13; ++p) {
            const int t0 = 2 * p, t1 = 2 * p + 1;
            const int sh0 = (t0 / 9) * 240 + ((t0 % 9) / 3) * 48 + (t0 % 3);
            const int sh1 = (t1 / 9) * 240 + ((t1 % 9) / 3) * 48 + (t1 % 3);
            float4 nf0, nf1;
            if (p < 12) { nf0 = fb[(2 * p + 2) * 32]; nf1 = fb[(2 * p + 3) * 32]; }
            else        { nf0 = fb[26 * 32]; }
            const uint32_t b00 = __float_as_uint(f0.x), b01 = __float_as_uint(f0.y);
            const uint32_t b02 = __float_as_uint(f0.z), b03 = __float_as_uint(f0.w);
            const uint32_t b10 = __float_as_uint(f1.x), b11 = __float_as_uint(f1.y);
            const uint32_t b12 = __float_as_uint(f1.z), b13 = __float_as_uint(f1.w);
            #pragma unroll
            for (int mt = 0; mt < 4; ++mt) {
                uint32_t a0 = sk[aOff[mt][0] + sh0];
                uint32_t a1 = sk[aOff[mt][1] + sh0];
                uint32_t a2 = sk[aOff[mt][0] + sh1];
                uint32_t a3 = sk[aOff[mt][1] + sh1];
                mma_k16(acc[mt][0], a0, a1, a2, a3, b00, b10);
                mma_k16(acc[mt][1], a0, a1, a2, a3, b01, b11);
                mma_k16(acc[mt][2], a0, a1, a2, a3, b02, b12);
                mma_k16(acc[mt][3], a0, a1, a2, a3, b03, b13);
            }
            f0 = nf0; f1 = nf1;
        }
        {   // tail: tap 26 (kd=2,kh=2,kw=2), k8; B in f0
            const int sh = 2 * 240 + 2 * 48 + 2;
            const uint32_t b0 = __float_as_uint(f0.x), b1 = __float_as_uint(f0.y);
            const uint32_t b2 = __float_as_uint(f0.z), b3 = __float_as_uint(f0.w);
            #pragma unroll
            for (int mt = 0; mt < 4; ++mt) {
                uint32_t a0 = sk[aOff[mt][0] + sh];
                uint32_t a1 = sk[aOff[mt][1] + sh];
                mma_k8(acc[mt][0], a0, a1, b0);
                mma_k8(acc[mt][1], a0, a1, b1);
                mma_k8(acc[mt][2], a0, a1, b2);
                mma_k8(acc[mt][3], a0, a1, b3);
            }
        }
    }

    // ---- epilogue: bias + masked scattered stores ----
    const int dyw = dy0 + dsel;
    #pragma unroll
    for (int mt = 0; mt < 4; ++mt) {
        #pragma unroll
        for (int j = 0; j < 2; ++j) {
            int r = mhalf * 64 + mt * 16 + g + j * 8;
            if (r >= 126) continue;
            int hl = r / 42, wi = r - hl * 42;
            if (wi >= 40) continue;
            int sp = dyw * 1600 + (h0 + hl) * 40 + wi;
            #pragma unroll
            for (int nt = 0; nt < 4; ++nt) {
                int co = nt * 8 + 2 * c;
                out[((b * 32 + co) * 16 + t) * 64000 + sp]     = acc[mt][nt][j * 2]     + sbias[co];
                out[((b * 32 + co + 1) * 16 + t) * 64000 + sp] = acc[mt][nt][j * 2 + 1] + sbias[co + 1];
            }
        }
    }
}

extern "C" void kernel_launch(void* const* d_in, const int* in_sizes, int n_in,
                              void* d_out, int out_size) {
    const float* x = nullptr; const float* w = nullptr; const float* bias = nullptr;
    for (int i = 0; i < n_in; ++i) {
        if (in_sizes[i] == 16384000)    x    = (const float*)d_in[i];
        else if (in_sizes[i] == 20736)  w    = (const float*)d_in[i];
        else if (in_sizes[i] == 96)     bias = (const float*)d_in[i];
    }
    float* out = (float*)d_out;
    prep_fB<<<(3 * 27 * 32 + 255) / 256, 256>>>(w);
    prep_x<<<32000, 256>>>(x);
    dim3 grid(14, 20, 32);
    conv4d_mma<<<grid, NT>>>(bias, out);
}

// round 17
// speedup vs baseline: 1.7760x; 1.0437x over previous
#include <cuda_runtime.h>
#include <cuda_fp16.h>
#include <cstdint>

// Conv4d via fp16 mma.sync m16n8k16 implicit GEMM, round 17.
// A operands fetched via ldmatrix.x4 (1 issue / 4 wavefronts per tap-pair per mt)
// from a k-interleaved slab [tf][dd][hh][ww44][cip4]; x pre-converted to half2
// in gmem as [b][t][d][h][w][cip] so cp.async staging is pure 16B copies.

__device__ __forceinline__ void mma_k16(float* d,
    uint32_t a0, uint32_t a1, uint32_t a2, uint32_t a3, uint32_t b0, uint32_t b1) {
    asm volatile("mma.sync.aligned.m16n8k16.row.col.f32.f16.f16.f32 "
                 "{%0,%1,%2,%3}, {%4,%5,%6,%7}, {%8,%9}, {%0,%1,%2,%3};"
                 : "+f"(d[0]), "+f"(d[1]), "+f"(d[2]), "+f"(d[3])
                 : "r"(a0), "r"(a1), "r"(a2), "r"(a3), "r"(b0), "r"(b1));
}
__device__ __forceinline__ void mma_k8(float* d,
    uint32_t a0, uint32_t a1, uint32_t b0) {
    asm volatile("mma.sync.aligned.m16n8k8.row.col.f32.f16.f16.f32 "
                 "{%0,%1,%2,%3}, {%4,%5}, {%6}, {%0,%1,%2,%3};"
                 : "+f"(d[0]), "+f"(d[1]), "+f"(d[2]), "+f"(d[3])
                 : "r"(a0), "r"(a1), "r"(b0));
}
__device__ __forceinline__ void ldsm_x4(uint32_t& r0, uint32_t& r1, uint32_t& r2,
                                        uint32_t& r3, uint32_t a) {
    asm volatile("ldmatrix.sync.aligned.m8n8.x4.shared.b16 {%0,%1,%2,%3}, [%4];"
                 : "=r"(r0), "=r"(r1), "=r"(r2), "=r"(r3) : "r"(a));
}
__device__ __forceinline__ void ldsm_x2(uint32_t& r0, uint32_t& r1, uint32_t a) {
    asm volatile("ldmatrix.sync.aligned.m8n8.x2.shared.b16 {%0,%1}, [%2];"
                 : "=r"(r0), "=r"(r1) : "r"(a));
}
__device__ __forceinline__ uint32_t smem_u32(const void* p) {
    uint32_t a;
    asm("{ .reg .u64 t; cvta.to.shared.u64 t, %1; cvt.u32.u64 %0, t; }" : "=r"(a) : "l"(p));
    return a;
}
__device__ __forceinline__ void cp_async16(uint32_t saddr, const void* gaddr) {
    asm volatile("cp.async.ca.shared.global [%0], [%1], 16;" :: "r"(saddr), "l"(gaddr));
}

// ---- pre-baked operands ----
// B fragments: [kt][slot27][lane32] float4; slot s, component nt:
//   half2( W[co=nt*8+g][ci=2c][tap=s], W[co=nt*8+g][ci=2c+1][tap=s] )
__device__ float4 g_fB[3 * 27 * 32];
// x as half2, k-interleaved: [b][t][d40][h40][w40][cip4]
__device__ uint32_t g_xh[2 * 16 * 64000 * 4];

__global__ void prep_fB(const float* __restrict__ weight) {
    int i = blockIdx.x * blockDim.x + threadIdx.x;
    if (i >= 3 * 27 * 32) return;
    int lane = i & 31;
    int slot = (i >> 5) % 27;
    int kt   = i / (27 * 32);
    int g = lane >> 2, c = lane & 3;
    uint32_t u[4];
    #pragma unroll
    for (int nt = 0; nt < 4; ++nt) {
        int co = nt * 8 + g;
        float wlo = weight[((kt * 32 + co) * 8 + 2 * c) * 27 + slot];
        float whi = weight[((kt * 32 + co) * 8 + 2 * c + 1) * 27 + slot];
        __half2 h = __floats2half2_rn(wlo, whi);
        u[nt] = *(uint32_t*)&h;
    }
    g_fB[(kt * 27 + slot) * 32 + lane] = *(float4*)u;
}

__global__ void prep_x(const float* __restrict__ x) {
    int i = blockIdx.x * blockDim.x + threadIdx.x;   // (b,t,pos)
    if (i >= 2 * 16 * 64000) return;
    int pos = i % 64000;
    int bt  = i / 64000;
    int t = bt & 15, b = bt >> 4;
    const float* p = x + b * 8192000 + t * 64000 + pos;
    uint32_t u[4];
    #pragma unroll
    for (int cip = 0; cip < 4; ++cip) {
        __half2 h = __floats2half2_rn(p[(2 * cip) * 1024000], p[(2 * cip + 1) * 1024000]);
        u[cip] = *(uint32_t*)&h;
    }
    *(uint4*)(g_xh + (size_t)i * 4) = *(uint4*)u;
}

#define NT 128
#define TFS_U32 (4 * 5 * 44 * 4)     // 3520 u32 per tf slab
#define TFS_B   (TFS_U32 * 4)        // 14080 bytes
// byte shift of tap within a tf slab (16B per w slot)
#define SHB(tap) ((((tap) / 9) * 220 + (((tap) % 9) / 3) * 44 + ((tap) % 3)) * 16)

__global__ void __launch_bounds__(NT, 4) conv4d_mma(
    const float* __restrict__ bias, float* __restrict__ out)
{
    __shared__ __align__(16) uint32_t slab[3 * TFS_U32];   // 42.2 KB
    __shared__ float sbias[32];

    const int tid  = threadIdx.x;
    const int wid  = tid >> 5, lane = tid & 31;
    const int g    = lane >> 2, c = lane & 3;
    const int lm   = lane & 15;                // ldmatrix row within 16
    const int tsel = lane >> 4;                // 0: tap t0 rows, 1: tap t1 rows
    const int dsel = wid >> 1;
    const int mhalf= wid & 1;

    const int hi  = blockIdx.x;                // 0..13
    const int dy0 = blockIdx.y * 2;
    const int bz  = blockIdx.z;
    const int h0  = (hi < 13) ? hi * 3 : 37;   // overlap rows recompute same values
    const int b   = bz >> 4;
    const int t   = bz & 15;

    if (tid < 32) {
        float s = 0.f;
        #pragma unroll
        for (int kt = 0; kt < 3; ++kt) {
            int tf = t + kt - 1;
            if (tf >= 0 && tf < 16) s += bias[kt * 32 + tid];
        }
        sbias[tid] = s;
    }
    for (int i = tid; i < 3 * TFS_U32; i += NT) slab[i] = 0u;   // halo stays 0

    // ldmatrix row base byte-addresses (per mt), for m = mhalf*64 + mt*16 + lm
    const uint32_t slab_s = smem_u32(slab);
    uint32_t rowByte[4];
    #pragma unroll
    for (int mt = 0; mt < 4; ++mt) {
        int m  = mhalf * 64 + mt * 16 + lm;
        int rr = (m < 126) ? m : 125;
        int hl = rr / 42, wi = rr - hl * 42;
        rowByte[mt] = slab_s + (uint32_t)(((dsel * 5 + hl) * 44 + wi) * 16);
    }

    float acc[4][4][4];
    #pragma unroll
    for (int mt = 0; mt < 4; ++mt)
        #pragma unroll
        for (int nt = 0; nt < 4; ++nt)
            #pragma unroll
            for (int k = 0; k < 4; ++k) acc[mt][nt][k] = 0.f;

    __syncthreads();   // zero-fill visible before cp.async writes land

    // ---- stage all valid tf slabs via cp.async: 16B = (w, cip0..3) ----
    #pragma unroll
    for (int kt = 0; kt < 3; ++kt) {
        const int tf = t + kt - 1;
        if ((unsigned)tf >= 16u) continue;
        const uint32_t* xg = g_xh + (size_t)(b * 16 + tf) * 256000;
        for (int idx = tid; idx < 800; idx += NT) {
            int gw = idx % 40;
            int r2 = idx / 40;               // 0..19
            int hh = r2 % 5, dd = r2 / 5;
            int gd = dy0 + dd - 1, gh = h0 + hh - 1;
            if ((unsigned)gd < 40u && (unsigned)gh < 40u) {
                const void* src = xg + ((size_t)gd * 1600 + gh * 40 + gw) * 4;
                uint32_t dst = slab_s + (uint32_t)(kt * TFS_B + ((dd * 5 + hh) * 44 + gw + 1) * 16);
                cp_async16(dst, src);
            }
        }
    }
    asm volatile("cp.async.commit_group;");
    asm volatile("cp.async.wait_group 0;" ::: "memory");
    __syncthreads();

    // ---- tap loops: per valid kt, 13 k16 pairs (ldmatrix.x4) + k8 tail ----
    #pragma unroll
    for (int kt = 0; kt < 3; ++kt) {
        const int tf = t + kt - 1;
        if ((unsigned)tf >= 16u) continue;
        const uint32_t ktoff = (uint32_t)(kt * TFS_B);
        const float4* fb = g_fB + (kt * 27) * 32 + lane;
        float4 f0 = fb[0];
        float4 f1 = fb[32];
        #pragma unroll
        for (int p = 0; p < 13; ++p) {
            const int t0 = 2 * p, t1 = 2 * p + 1;
            const uint32_t off = ktoff + (tsel ? SHB(t1) : SHB(t0));
            float4 nf0, nf1;
            if (p < 12) { nf0 = fb[(2 * p + 2) * 32]; nf1 = fb[(2 * p + 3) * 32]; }
            else        { nf0 = fb[26 * 32]; }
            const uint32_t b00 = __float_as_uint(f0.x), b01 = __float_as_uint(f0.y);
            const uint32_t b02 = __float_as_uint(f0.z), b03 = __float_as_uint(f0.w);
            const uint32_t b10 = __float_as_uint(f1.x), b11 = __float_as_uint(f1.y);
            const uint32_t b12 = __float_as_uint(f1.z), b13 = __float_as_uint(f1.w);
            #pragma unroll
            for (int mt = 0; mt < 4; ++mt) {
                uint32_t a0, a1, a2, a3;
                ldsm_x4(a0, a1, a2, a3, rowByte[mt] + off);
                mma_k16(acc[mt][0], a0, a1, a2, a3, b00, b10);
                mma_k16(acc[mt][1], a0, a1, a2, a3, b01, b11);
                mma_k16(acc[mt][2], a0, a1, a2, a3, b02, b12);
                mma_k16(acc[mt][3], a0, a1, a2, a3, b03, b13);
            }
            f0 = nf0; f1 = nf1;
        }
        {   // tail: tap 26, k8; B in f0
            const uint32_t off = ktoff + SHB(26);
            const uint32_t b0 = __float_as_uint(f0.x), b1 = __float_as_uint(f0.y);
            const uint32_t b2 = __float_as_uint(f0.z), b3 = __float_as_uint(f0.w);
            #pragma unroll
            for (int mt = 0; mt < 4; ++mt) {
                uint32_t a0, a1;
                ldsm_x2(a0, a1, rowByte[mt] + off);
                mma_k8(acc[mt][0], a0, a1, b0);
                mma_k8(acc[mt][1], a0, a1, b1);
                mma_k8(acc[mt][2], a0, a1, b2);
                mma_k8(acc[mt][3], a0, a1, b3);
            }
        }
    }

    // ---- epilogue: bias + masked scattered stores ----
    const int dyw = dy0 + dsel;
    #pragma unroll
    for (int mt = 0; mt < 4; ++mt) {
        #pragma unroll
        for (int j = 0; j < 2; ++j) {
            int r = mhalf * 64 + mt * 16 + g + j * 8;
            if (r >= 126) continue;
            int hl = r / 42, wi = r - hl * 42;
            if (wi >= 40) continue;
            int sp = dyw * 1600 + (h0 + hl) * 40 + wi;
            #pragma unroll
            for (int nt = 0; nt < 4; ++nt) {
                int co = nt * 8 + 2 * c;
                out[((b * 32 + co) * 16 + t) * 64000 + sp]     = acc[mt][nt][j * 2]     + sbias[co];
                out[((b * 32 + co + 1) * 16 + t) * 64000 + sp] = acc[mt][nt][j * 2 + 1] + sbias[co + 1];
            }
        }
    }
}

extern "C" void kernel_launch(void* const* d_in, const int* in_sizes, int n_in,
                              void* d_out, int out_size) {
    const float* x = nullptr; const float* w = nullptr; const float* bias = nullptr;
    for (int i = 0; i < n_in; ++i) {
        if (in_sizes[i] == 16384000)    x    = (const float*)d_in[i];
        else if (in_sizes[i] == 20736)  w    = (const float*)d_in[i];
        else if (in_sizes[i] == 96)     bias = (const float*)d_in[i];
    }
    float* out = (float*)d_out;
    prep_fB<<<(3 * 27 * 32 + 255) / 256, 256>>>(w);
    prep_x<<<(2 * 16 * 64000 + 255) / 256, 256>>>(x);
    dim3 grid(14, 20, 32);
    conv4d_mma<<<grid, NT>>>(bias, out);
}